// round 1
// baseline (speedup 1.0000x reference)
#include <cuda_runtime.h>

// ---------------------------------------------------------------------------
// BEEncdecMultiheadAttn: Tq=Tk=1024, B=8, H=1024, heads=16, hd=64
// Round 0: correct fp32 baseline. 3 SGEMM launches + 1 flash-attn launch.
// Scratch lives in __device__ globals (allocation-free, graph-capturable).
// ---------------------------------------------------------------------------

namespace {
constexpr int TQ  = 1024;
constexpr int TK  = 1024;
constexpr int B   = 8;
constexpr int H   = 1024;
constexpr int BH  = B * H;        // 8192
constexpr int B2H = 2 * B * H;    // 16384
}

__device__ float g_q  [TQ * B * H];       // (Tq, B, H)         32 MB
__device__ float g_kv [TK * B * 2 * H];   // (Tk, B, 2H)        64 MB
__device__ float g_ctx[TQ * B * H];       // (Tq, B, H)         32 MB

// ---------------------------------------------------------------------------
// C[m, o] = ( sum_h A[m,h] * r[h] * W[o,h] ) * s[o] + bias[o]
// A: M x K (row-major, stride lda), W: N x K row-major (ldb = K = 1024)
// blockIdx.z = batch index; per-batch element strides for A/C/r/s.
// 128x128 block tile, K-tile 8, 256 threads, 8x8 per-thread micro-tile.
// ---------------------------------------------------------------------------
__global__ __launch_bounds__(256) void gemm_nt_kernel(
    const float* __restrict__ A, int lda, int strideAb,
    const float* __restrict__ W,
    float* __restrict__ C, int ldc, int strideCb,
    const float* __restrict__ rvec, int strideRb,
    const float* __restrict__ svec, int strideSb,
    const float* __restrict__ bias)
{
    constexpr int K = 1024;
    __shared__ float As[8][128];
    __shared__ float Bs[8][128];

    const int tid = threadIdx.x;
    const int tx  = tid & 15;
    const int ty  = tid >> 4;
    const int m0  = blockIdx.y * 128;
    const int n0  = blockIdx.x * 128;
    const int z   = blockIdx.z;

    A += (size_t)z * strideAb;
    C += (size_t)z * strideCb;
    const float* rb = rvec ? rvec + (size_t)z * strideRb : nullptr;

    const int lrow = tid >> 1;        // 0..127
    const int lk   = (tid & 1) * 4;   // 0 or 4

    float acc[8][8];
#pragma unroll
    for (int i = 0; i < 8; i++)
#pragma unroll
        for (int j = 0; j < 8; j++) acc[i][j] = 0.f;

    const float* Aptr = A + (size_t)(m0 + lrow) * lda + lk;
    const float* Wptr = W + (size_t)(n0 + lrow) * K + lk;

    for (int k0 = 0; k0 < K; k0 += 8) {
        float4 av = *(const float4*)(Aptr + k0);
        if (rb) {
            float4 rv = *(const float4*)(rb + k0 + lk);
            av.x *= rv.x; av.y *= rv.y; av.z *= rv.z; av.w *= rv.w;
        }
        As[lk + 0][lrow] = av.x;
        As[lk + 1][lrow] = av.y;
        As[lk + 2][lrow] = av.z;
        As[lk + 3][lrow] = av.w;

        float4 bv = *(const float4*)(Wptr + k0);
        Bs[lk + 0][lrow] = bv.x;
        Bs[lk + 1][lrow] = bv.y;
        Bs[lk + 2][lrow] = bv.z;
        Bs[lk + 3][lrow] = bv.w;
        __syncthreads();

#pragma unroll
        for (int kk = 0; kk < 8; kk++) {
            float4 a0 = *(const float4*)&As[kk][ty * 8];
            float4 a1 = *(const float4*)&As[kk][ty * 8 + 4];
            float4 b0 = *(const float4*)&Bs[kk][tx * 8];
            float4 b1 = *(const float4*)&Bs[kk][tx * 8 + 4];
            float a[8] = {a0.x, a0.y, a0.z, a0.w, a1.x, a1.y, a1.z, a1.w};
            float b[8] = {b0.x, b0.y, b0.z, b0.w, b1.x, b1.y, b1.z, b1.w};
#pragma unroll
            for (int i = 0; i < 8; i++)
#pragma unroll
                for (int j = 0; j < 8; j++)
                    acc[i][j] += a[i] * b[j];
        }
        __syncthreads();
    }

    const float* sb = svec ? svec + (size_t)z * strideSb : nullptr;
#pragma unroll
    for (int i = 0; i < 8; i++) {
        const int row = m0 + ty * 8 + i;
#pragma unroll
        for (int jv = 0; jv < 8; jv += 4) {
            const int col = n0 + tx * 8 + jv;
            float4 v = make_float4(acc[i][jv], acc[i][jv + 1], acc[i][jv + 2], acc[i][jv + 3]);
            if (sb) {
                v.x *= sb[col]; v.y *= sb[col + 1]; v.z *= sb[col + 2]; v.w *= sb[col + 3];
            }
            if (bias) {
                v.x += bias[col]; v.y += bias[col + 1]; v.z += bias[col + 2]; v.w += bias[col + 3];
            }
            *(float4*)(C + (size_t)row * ldc + col) = v;
        }
    }
}

// ---------------------------------------------------------------------------
// Flash attention, fp32. One block per (q-tile of 64, head-batch n).
// Q view:      g_q [t*8192 + n*64  + d]
// K view:      g_kv[k*16384 + n*128 + d]
// V view:      g_kv[k*16384 + n*128 + 64 + d]
// ctx output:  g_ctx[t*8192 + n*64 + d]
// 256 threads = 16x16; each thread owns a 4x4 fragment of S/P and of O.
// Row statistics reduced over the 16-thread half-warp row group.
// ---------------------------------------------------------------------------
__global__ __launch_bounds__(256) void attn_kernel(
    const float* __restrict__ q, const float* __restrict__ kv, float* __restrict__ ctx)
{
    extern __shared__ float sm[];
    float* Qt = sm;              // [d][q] 64x64 (transposed, pre-scaled)
    float* Kt = sm + 4096;       // [d][k] 64x64 (transposed)
    float* Vs = sm + 8192;       // [k][d] 64x64
    float* Pt = sm + 12288;      // [k][q] 64x64

    const int tid = threadIdx.x;
    const int tx  = tid & 15;
    const int ty  = tid >> 4;
    const int n   = blockIdx.y;
    const int q0  = blockIdx.x * 64;

    // Load Q tile transposed into smem, folding the 1/sqrt(hd) scale.
    {
        const int r  = tid >> 2;          // 0..63
        const int c0 = (tid & 3) * 16;    // 0,16,32,48
        const float* qp = q + (size_t)(q0 + r) * BH + n * 64 + c0;
#pragma unroll
        for (int ii = 0; ii < 4; ii++) {
            float4 v = *(const float4*)(qp + ii * 4);
            const int c = c0 + ii * 4;
            Qt[(c + 0) * 64 + r] = v.x * 0.125f;
            Qt[(c + 1) * 64 + r] = v.y * 0.125f;
            Qt[(c + 2) * 64 + r] = v.z * 0.125f;
            Qt[(c + 3) * 64 + r] = v.w * 0.125f;
        }
    }

    float m_i[4], l_i[4], O[4][4];
#pragma unroll
    for (int i = 0; i < 4; i++) {
        m_i[i] = -1e30f;
        l_i[i] = 0.f;
#pragma unroll
        for (int j = 0; j < 4; j++) O[i][j] = 0.f;
    }

    for (int k0 = 0; k0 < TK; k0 += 64) {
        // Load K (transposed) and V (natural) tiles.
        {
            const int r  = tid >> 2;
            const int c0 = (tid & 3) * 16;
            const float* kp = kv + (size_t)(k0 + r) * B2H + n * 128 + c0;
#pragma unroll
            for (int ii = 0; ii < 4; ii++) {
                float4 v = *(const float4*)(kp + ii * 4);
                const int c = c0 + ii * 4;
                Kt[(c + 0) * 64 + r] = v.x;
                Kt[(c + 1) * 64 + r] = v.y;
                Kt[(c + 2) * 64 + r] = v.z;
                Kt[(c + 3) * 64 + r] = v.w;
            }
            const float* vp = kp + 64;
#pragma unroll
            for (int ii = 0; ii < 4; ii++) {
                *(float4*)&Vs[r * 64 + c0 + ii * 4] = *(const float4*)(vp + ii * 4);
            }
        }
        __syncthreads();

        // S = (Q*scale) @ K^T  — 4x4 fragment per thread
        float S[4][4];
#pragma unroll
        for (int i = 0; i < 4; i++)
#pragma unroll
            for (int j = 0; j < 4; j++) S[i][j] = 0.f;

#pragma unroll 8
        for (int d = 0; d < 64; d++) {
            float4 a = *(const float4*)&Qt[d * 64 + ty * 4];
            float4 b = *(const float4*)&Kt[d * 64 + tx * 4];
            float av[4] = {a.x, a.y, a.z, a.w};
            float bv[4] = {b.x, b.y, b.z, b.w};
#pragma unroll
            for (int i = 0; i < 4; i++)
#pragma unroll
                for (int j = 0; j < 4; j++)
                    S[i][j] += av[i] * bv[j];
        }

        // Online softmax: reduce over the 16-thread row group (half warp).
#pragma unroll
        for (int i = 0; i < 4; i++) {
            float t = fmaxf(fmaxf(S[i][0], S[i][1]), fmaxf(S[i][2], S[i][3]));
#pragma unroll
            for (int off = 8; off >= 1; off >>= 1)
                t = fmaxf(t, __shfl_xor_sync(0xffffffffu, t, off));
            const float mn   = fmaxf(m_i[i], t);
            const float corr = __expf(m_i[i] - mn);
            m_i[i] = mn;
            float rs = 0.f;
#pragma unroll
            for (int j = 0; j < 4; j++) {
                S[i][j] = __expf(S[i][j] - mn);
                rs += S[i][j];
            }
#pragma unroll
            for (int off = 8; off >= 1; off >>= 1)
                rs += __shfl_xor_sync(0xffffffffu, rs, off);
            l_i[i] = l_i[i] * corr + rs;
#pragma unroll
            for (int j = 0; j < 4; j++) O[i][j] *= corr;
        }

        // P -> smem (transposed as [k][q]) for the PV GEMM.
#pragma unroll
        for (int i = 0; i < 4; i++)
#pragma unroll
            for (int j = 0; j < 4; j++)
                Pt[(tx * 4 + j) * 64 + ty * 4 + i] = S[i][j];
        __syncthreads();

        // O += P @ V
#pragma unroll 4
        for (int k = 0; k < 64; k++) {
            float4 a = *(const float4*)&Pt[k * 64 + ty * 4];
            float4 b = *(const float4*)&Vs[k * 64 + tx * 4];
            float av[4] = {a.x, a.y, a.z, a.w};
            float bv[4] = {b.x, b.y, b.z, b.w};
#pragma unroll
            for (int i = 0; i < 4; i++)
#pragma unroll
                for (int j = 0; j < 4; j++)
                    O[i][j] += av[i] * bv[j];
        }
        __syncthreads();
    }

    // Finalize: O /= l, write ctx.
#pragma unroll
    for (int i = 0; i < 4; i++) {
        const float inv = 1.f / l_i[i];
        const int row = q0 + ty * 4 + i;
        float4 v = make_float4(O[i][0] * inv, O[i][1] * inv, O[i][2] * inv, O[i][3] * inv);
        *(float4*)(ctx + (size_t)row * BH + n * 64 + tx * 4) = v;
    }
}

// ---------------------------------------------------------------------------
extern "C" void kernel_launch(void* const* d_in, const int* in_sizes, int n_in,
                              void* d_out, int out_size)
{
    const float* inputs_q  = (const float*)d_in[0];
    const float* inputs_kv = (const float*)d_in[1];
    const float* w_q  = (const float*)d_in[2];
    const float* b_q  = (const float*)d_in[3];
    const float* w_kv = (const float*)d_in[4];
    const float* b_kv = (const float*)d_in[5];
    const float* w_o  = (const float*)d_in[6];
    const float* b_o  = (const float*)d_in[7];
    const float* r_q  = (const float*)d_in[8];
    const float* s_q  = (const float*)d_in[9];
    const float* r_kv = (const float*)d_in[10];
    const float* s_kv = (const float*)d_in[11];
    float* out = (float*)d_out;

    void* p;
    cudaGetSymbolAddress(&p, g_q);   float* gq   = (float*)p;
    cudaGetSymbolAddress(&p, g_kv);  float* gkv  = (float*)p;
    cudaGetSymbolAddress(&p, g_ctx); float* gctx = (float*)p;

    dim3 blk(256);

    // q projection: per-batch (Tq x H) @ w_q^T, r/s/b fused
    gemm_nt_kernel<<<dim3(8, 8, 8), blk>>>(
        inputs_q, BH, H, w_q, gq, BH, H, r_q, H, s_q, H, b_q);

    // kv projection: per-batch (Tk x 2H) @ w_kv^T, r/s/b fused
    gemm_nt_kernel<<<dim3(16, 8, 8), blk>>>(
        inputs_kv, BH, H, w_kv, gkv, B2H, 2 * H, r_kv, H, s_kv, 2 * H, b_kv);

    // attention: 128 head-batches x 16 q-tiles
    cudaFuncSetAttribute(attn_kernel, cudaFuncAttributeMaxDynamicSharedMemorySize, 65536);
    attn_kernel<<<dim3(16, 128), blk, 65536>>>(gq, gkv, gctx);

    // output projection: (Tq*B x H) @ w_o^T + b_o
    gemm_nt_kernel<<<dim3(8, 64, 1), blk>>>(
        gctx, H, 0, w_o, out, H, 0, nullptr, 0, nullptr, 0, b_o);
}

// round 3
// speedup vs baseline: 3.0777x; 3.0777x over previous
#include <cuda_runtime.h>
#include <cuda_bf16.h>
#include <cstdint>

// ---------------------------------------------------------------------------
// BEEncdecMultiheadAttn: Tq=Tk=1024, B=8, H=1024, heads=16, hd=64
// Round 3: everything on mma.sync bf16 (hi/lo 3-term split). No tcgen05
// (PTX target is plain sm_103 — arch-suffix features unavailable).
// ---------------------------------------------------------------------------

namespace {
constexpr int TQ = 1024, TK = 1024, B = 8, H = 1024, K = 1024;
}

// bf16 hi/lo scratch (device globals: allocation-free)
__device__ __nv_bfloat16 g_aq_h [B * TQ * H], g_aq_l [B * TQ * H];
__device__ __nv_bfloat16 g_akv_h[B * TK * H], g_akv_l[B * TK * H];
__device__ __nv_bfloat16 g_wq_h [H * H],      g_wq_l [H * H];
__device__ __nv_bfloat16 g_wkv_h[2 * H * H],  g_wkv_l[2 * H * H];
__device__ __nv_bfloat16 g_wo_h [H * H],      g_wo_l [H * H];
__device__ __nv_bfloat16 g_qh [B * TQ * H],      g_ql [B * TQ * H];       // [b][t][H]
__device__ __nv_bfloat16 g_kvh[B * TK * 2 * H],  g_kvl[B * TK * 2 * H];   // [b][t][2H]
__device__ __nv_bfloat16 g_cxh[TQ * B * H],      g_cxl[TQ * B * H];       // [t][b][H]

// ---------------------------------------------------------------------------
// low-level helpers (all sm_80+ baseline PTX)
// ---------------------------------------------------------------------------
__device__ __forceinline__ uint32_t smem_u32(const void* p) {
    uint32_t a;
    asm("{ .reg .u64 t; cvta.to.shared.u64 t, %1; cvt.u32.u64 %0, t; }" : "=r"(a) : "l"(p));
    return a;
}
__device__ __forceinline__ void cpa16(uint32_t dst, const void* src) {
    asm volatile("cp.async.cg.shared.global [%0], [%1], 16;" :: "r"(dst), "l"(src));
}
__device__ __forceinline__ void cpa_commit() { asm volatile("cp.async.commit_group;" ::: "memory"); }
__device__ __forceinline__ void cpa_wait0()  { asm volatile("cp.async.wait_group 0;" ::: "memory"); }

__device__ __forceinline__ void ldsm4(uint32_t r[4], uint32_t addr) {
    asm volatile("ldmatrix.sync.aligned.m8n8.x4.shared.b16 {%0,%1,%2,%3}, [%4];"
                 : "=r"(r[0]), "=r"(r[1]), "=r"(r[2]), "=r"(r[3]) : "r"(addr));
}
__device__ __forceinline__ void ldsm4t(uint32_t r[4], uint32_t addr) {
    asm volatile("ldmatrix.sync.aligned.m8n8.x4.trans.shared.b16 {%0,%1,%2,%3}, [%4];"
                 : "=r"(r[0]), "=r"(r[1]), "=r"(r[2]), "=r"(r[3]) : "r"(addr));
}
__device__ __forceinline__ void mma16816(float c[4], const uint32_t a[4], uint32_t b0, uint32_t b1) {
    asm volatile(
        "mma.sync.aligned.m16n8k16.row.col.f32.bf16.bf16.f32 "
        "{%0,%1,%2,%3}, {%4,%5,%6,%7}, {%8,%9}, {%0,%1,%2,%3};"
        : "+f"(c[0]), "+f"(c[1]), "+f"(c[2]), "+f"(c[3])
        : "r"(a[0]), "r"(a[1]), "r"(a[2]), "r"(a[3]), "r"(b0), "r"(b1));
}
__device__ __forceinline__ float ex2(float x) {
    float y; asm("ex2.approx.ftz.f32 %0, %1;" : "=f"(y) : "f"(x)); return y;
}
__device__ __forceinline__ uint32_t pack_bf2(__nv_bfloat16 x, __nv_bfloat16 y) {
    __nv_bfloat162 t = __halves2bfloat162(x, y);
    return *reinterpret_cast<uint32_t*>(&t);
}
__device__ __forceinline__ void pack_hilo(float a, float b, uint32_t& h, uint32_t& l) {
    __nv_bfloat16 ha = __float2bfloat16_rn(a), hb = __float2bfloat16_rn(b);
    __nv_bfloat16 la = __float2bfloat16_rn(a - __bfloat162float(ha));
    __nv_bfloat16 lb = __float2bfloat16_rn(b - __bfloat162float(hb));
    h = pack_bf2(ha, hb);
    l = pack_bf2(la, lb);
}

// ---------------------------------------------------------------------------
// split kernels
// ---------------------------------------------------------------------------
__device__ __forceinline__ void split2(float x, __nv_bfloat16& h, __nv_bfloat16& l) {
    h = __float2bfloat16_rn(x);
    l = __float2bfloat16_rn(x - __bfloat162float(h));
}

// x [T][B][H] * r [B][H] -> hi/lo [B][T][H]
__global__ __launch_bounds__(256) void split_act_kernel(
    const float* __restrict__ x, const float* __restrict__ r,
    __nv_bfloat16* __restrict__ hi, __nv_bfloat16* __restrict__ lo, int T)
{
    const int i = blockIdx.x * blockDim.x + threadIdx.x;
    if (i >= T * B * H / 4) return;
    const int e = i * 4, h = e % H, tb = e / H, b = tb % B, t = tb / B;
    float4 xv = ((const float4*)x)[i];
    float4 rv = *(const float4*)(r + b * H + h);
    xv.x *= rv.x; xv.y *= rv.y; xv.z *= rv.z; xv.w *= rv.w;
    __nv_bfloat16 h0, h1, h2, h3, l0, l1, l2, l3;
    split2(xv.x, h0, l0); split2(xv.y, h1, l1); split2(xv.z, h2, l2); split2(xv.w, h3, l3);
    const size_t o = ((size_t)b * T + t) * H + h;
    *(__nv_bfloat162*)(hi + o)     = __halves2bfloat162(h0, h1);
    *(__nv_bfloat162*)(hi + o + 2) = __halves2bfloat162(h2, h3);
    *(__nv_bfloat162*)(lo + o)     = __halves2bfloat162(l0, l1);
    *(__nv_bfloat162*)(lo + o + 2) = __halves2bfloat162(l2, l3);
}

__global__ __launch_bounds__(256) void split_plain_kernel(
    const float* __restrict__ x,
    __nv_bfloat16* __restrict__ hi, __nv_bfloat16* __restrict__ lo, int total4)
{
    const int i = blockIdx.x * blockDim.x + threadIdx.x;
    if (i >= total4) return;
    float4 xv = ((const float4*)x)[i];
    __nv_bfloat16 h0, h1, h2, h3, l0, l1, l2, l3;
    split2(xv.x, h0, l0); split2(xv.y, h1, l1); split2(xv.z, h2, l2); split2(xv.w, h3, l3);
    const size_t o = (size_t)i * 4;
    *(__nv_bfloat162*)(hi + o)     = __halves2bfloat162(h0, h1);
    *(__nv_bfloat162*)(hi + o + 2) = __halves2bfloat162(h2, h3);
    *(__nv_bfloat162*)(lo + o)     = __halves2bfloat162(l0, l1);
    *(__nv_bfloat162*)(lo + o + 2) = __halves2bfloat162(l2, l3);
}

// ---------------------------------------------------------------------------
// GEMM: C[m,n] = sum_k (Ah+Al)[m,k] * (Wh+Wl)[n,k]   (3-term bf16)
// then C = C*s[n] + bias[n]. Output either fp32 (Cf) or bf16 hi/lo (Chi/Clo).
// Block tile 128x128, K-chunk 64, cp.async double buffer, 8 warps (2m x 4n),
// warp tile 64x32.  smem row stride: 64+8=72 bf16 (144B) — ldmatrix conflict-free.
// ---------------------------------------------------------------------------
namespace {
constexpr int GSTR   = 144;            // smem row stride bytes
constexpr int GTILE  = 128 * GSTR;     // 18432 B per tile
constexpr int GBUF   = 4 * GTILE;      // Ah, Al, Wh, Wl
constexpr int GEMM_SMEM = 2 * GBUF;    // 147456
}

__global__ __launch_bounds__(256) void gemm_mma_kernel(
    const __nv_bfloat16* __restrict__ ah, const __nv_bfloat16* __restrict__ al,
    const __nv_bfloat16* __restrict__ wh, const __nv_bfloat16* __restrict__ wl,
    int Mb,
    float* __restrict__ Cf, __nv_bfloat16* __restrict__ Chi, __nv_bfloat16* __restrict__ Clo,
    int ldc, long long strideCb,
    const float* __restrict__ svec, int sStride, const float* __restrict__ bias)
{
    extern __shared__ char smraw[];
    const uint32_t sb = smem_u32(smraw);

    const int tid = threadIdx.x, lane = tid & 31, wid = tid >> 5;
    const int wm = wid & 1, wn = wid >> 1;
    const int n0 = blockIdx.x * 128, m0 = blockIdx.y * 128, z = blockIdx.z;

    const __nv_bfloat16* Ah = ah + (size_t)z * Mb * K + (size_t)m0 * K;
    const __nv_bfloat16* Al = al + (size_t)z * Mb * K + (size_t)m0 * K;
    const __nv_bfloat16* Wh = wh + (size_t)n0 * K;
    const __nv_bfloat16* Wl = wl + (size_t)n0 * K;

    float acc[4][4][4];
#pragma unroll
    for (int a = 0; a < 4; a++)
#pragma unroll
        for (int b = 0; b < 4; b++)
#pragma unroll
            for (int c = 0; c < 4; c++) acc[a][b][c] = 0.f;

    auto issue_chunk = [&](int c, int buf) {
        const uint32_t base = sb + buf * GBUF;
        const __nv_bfloat16* srcs[4] = { Ah + c * 64, Al + c * 64, Wh + c * 64, Wl + c * 64 };
#pragma unroll
        for (int arr = 0; arr < 4; arr++) {
#pragma unroll
            for (int i = 0; i < 4; i++) {
                const int id = tid + i * 256;
                const int row = id >> 3, cc = id & 7;
                cpa16(base + arr * GTILE + row * GSTR + cc * 16,
                      srcs[arr] + (size_t)row * K + cc * 8);
            }
        }
        cpa_commit();
    };

    issue_chunk(0, 0);

    for (int c = 0; c < 16; c++) {
        cpa_wait0();
        __syncthreads();
        if (c + 1 < 16) issue_chunk(c + 1, (c + 1) & 1);

        const uint32_t bufb = sb + (c & 1) * GBUF;
#pragma unroll
        for (int ks = 0; ks < 4; ks++) {
            uint32_t a_h[4][4], a_l[4][4];
#pragma unroll
            for (int mt = 0; mt < 4; mt++) {
                const uint32_t ra = bufb +
                    (wm * 64 + mt * 16 + (lane & 15)) * GSTR +
                    (ks * 16 + (lane >> 4) * 8) * 2;
                ldsm4(a_h[mt], ra);
                ldsm4(a_l[mt], ra + GTILE);
            }
#pragma unroll
            for (int nt2 = 0; nt2 < 2; nt2++) {
                const uint32_t rb = bufb + 2 * GTILE +
                    (wn * 32 + nt2 * 16 + (lane & 7) + ((lane >> 4) & 1) * 8) * GSTR +
                    (ks * 16 + ((lane >> 3) & 1) * 8) * 2;
                uint32_t bh[4], bl[4];
                ldsm4(bh, rb);
                ldsm4(bl, rb + GTILE);
#pragma unroll
                for (int mt = 0; mt < 4; mt++) {
                    mma16816(acc[mt][2 * nt2],     a_h[mt], bh[0], bh[1]);
                    mma16816(acc[mt][2 * nt2],     a_h[mt], bl[0], bl[1]);
                    mma16816(acc[mt][2 * nt2],     a_l[mt], bh[0], bh[1]);
                    mma16816(acc[mt][2 * nt2 + 1], a_h[mt], bh[2], bh[3]);
                    mma16816(acc[mt][2 * nt2 + 1], a_h[mt], bl[2], bl[3]);
                    mma16816(acc[mt][2 * nt2 + 1], a_l[mt], bh[2], bh[3]);
                }
            }
        }
        __syncthreads();
    }

    // epilogue
    const long long cb = (long long)z * strideCb;
    const int g = lane >> 2, tq = (lane & 3) * 2;
#pragma unroll
    for (int mt = 0; mt < 4; mt++) {
#pragma unroll
        for (int nt = 0; nt < 4; nt++) {
            const int row0 = m0 + wm * 64 + mt * 16 + g;
            const int col  = n0 + wn * 32 + nt * 8 + tq;
            float sv0 = 1.f, sv1 = 1.f, bv0 = 0.f, bv1 = 0.f;
            if (svec) {
                sv0 = __ldg(svec + (size_t)z * sStride + col);
                sv1 = __ldg(svec + (size_t)z * sStride + col + 1);
            }
            if (bias) { bv0 = __ldg(bias + col); bv1 = __ldg(bias + col + 1); }
            const float v0 = acc[mt][nt][0] * sv0 + bv0;
            const float v1 = acc[mt][nt][1] * sv1 + bv1;
            const float v2 = acc[mt][nt][2] * sv0 + bv0;
            const float v3 = acc[mt][nt][3] * sv1 + bv1;
            const size_t i0 = (size_t)(cb + (long long)row0 * ldc + col);
            const size_t i1 = i0 + (size_t)8 * ldc;
            if (Cf) {
                *(float2*)(Cf + i0) = make_float2(v0, v1);
                *(float2*)(Cf + i1) = make_float2(v2, v3);
            } else {
                uint32_t h, l;
                pack_hilo(v0, v1, h, l);
                *(uint32_t*)(Chi + i0) = h; *(uint32_t*)(Clo + i0) = l;
                pack_hilo(v2, v3, h, l);
                *(uint32_t*)(Chi + i1) = h; *(uint32_t*)(Clo + i1) = l;
            }
        }
    }
}

// ---------------------------------------------------------------------------
// Flash attention on mma.sync. Block = (q-tile 128, head-batch n). 8 warps,
// warp owns 16 q-rows x all 128 k-cols per iteration. hd=64, KV block 128.
// S = QK^T 3-term; softmax in exp2 domain; P kept in registers (acc layout
// == A-fragment layout); PV 3-term (Ph@Vh + Pl@Vh + Ph@Vl).
// ---------------------------------------------------------------------------
namespace {
constexpr int ASTR = 144;                   // smem row stride bytes (64+8 bf16)
constexpr int ATILE = 128 * ASTR;           // 18432
constexpr int ATTN_SMEM = 6 * ATILE;        // Qh Ql Kh Kl Vh Vl = 110592
constexpr float SC = 0.125f * 1.44269504f;  // hd^-0.5 * log2(e)
}

__global__ __launch_bounds__(256) void attn_mma_kernel(
    const __nv_bfloat16* __restrict__ qh_, const __nv_bfloat16* __restrict__ ql_,
    const __nv_bfloat16* __restrict__ kvh_, const __nv_bfloat16* __restrict__ kvl_,
    __nv_bfloat16* __restrict__ cxh, __nv_bfloat16* __restrict__ cxl)
{
    extern __shared__ char smraw[];
    const uint32_t sb = smem_u32(smraw);
    const uint32_t QH = 0, QL = ATILE, KH = 2 * ATILE, KL = 3 * ATILE,
                   VH = 4 * ATILE, VL = 5 * ATILE;

    const int tid = threadIdx.x, lane = tid & 31, wid = tid >> 5;
    const int n = blockIdx.y, b = n >> 4, j = n & 15;
    const int q0 = blockIdx.x * 128;

    // load Q tile (128 x 64 hi/lo)
    {
        const __nv_bfloat16* s0 = qh_ + ((size_t)(b * TQ + q0)) * H + j * 64;
        const __nv_bfloat16* s1 = ql_ + ((size_t)(b * TQ + q0)) * H + j * 64;
#pragma unroll
        for (int i = 0; i < 4; i++) {
            const int id = tid + i * 256;
            const int row = id >> 3, cc = id & 7;
            cpa16(sb + QH + row * ASTR + cc * 16, s0 + (size_t)row * H + cc * 8);
            cpa16(sb + QL + row * ASTR + cc * 16, s1 + (size_t)row * H + cc * 8);
        }
        cpa_commit(); cpa_wait0();
        __syncthreads();
    }

    // Q fragments resident in registers (4 k16-tiles, hi+lo)
    uint32_t qfh[4][4], qfl[4][4];
#pragma unroll
    for (int kt = 0; kt < 4; kt++) {
        const uint32_t ra = sb + QH + (wid * 16 + (lane & 15)) * ASTR +
                            (kt * 16 + (lane >> 4) * 8) * 2;
        ldsm4(qfh[kt], ra);
        ldsm4(qfl[kt], ra + (QL - QH));
    }

    float O[8][4];
#pragma unroll
    for (int d = 0; d < 8; d++)
#pragma unroll
        for (int e = 0; e < 4; e++) O[d][e] = 0.f;
    float mrow0 = -1e30f, mrow1 = -1e30f, lrow0 = 0.f, lrow1 = 0.f;

    for (int kb = 0; kb < 8; kb++) {
        // load K/V tiles (128 x 64 each, hi/lo)
        {
            const size_t base = ((size_t)(b * TK + kb * 128)) * 2048 + j * 128;
#pragma unroll
            for (int i = 0; i < 4; i++) {
                const int id = tid + i * 256;
                const int row = id >> 3, cc = id & 7;
                const size_t gsrc = base + (size_t)row * 2048 + cc * 8;
                const uint32_t sof = row * ASTR + cc * 16;
                cpa16(sb + KH + sof, kvh_ + gsrc);
                cpa16(sb + KL + sof, kvl_ + gsrc);
                cpa16(sb + VH + sof, kvh_ + gsrc + 64);
                cpa16(sb + VL + sof, kvl_ + gsrc + 64);
            }
            cpa_commit(); cpa_wait0();
            __syncthreads();
        }

        // ---- S = Q @ K^T (3-term) : 16 n8-tiles of fp32 acc ----
        float S[16][4];
#pragma unroll
        for (int t = 0; t < 16; t++)
#pragma unroll
            for (int e = 0; e < 4; e++) S[t][e] = 0.f;

#pragma unroll
        for (int nt2 = 0; nt2 < 8; nt2++) {
#pragma unroll
            for (int dt = 0; dt < 4; dt++) {
                const uint32_t rb = sb + KH +
                    (nt2 * 16 + (lane & 7) + ((lane >> 4) & 1) * 8) * ASTR +
                    (dt * 16 + ((lane >> 3) & 1) * 8) * 2;
                uint32_t bh[4], bl[4];
                ldsm4(bh, rb);
                ldsm4(bl, rb + (KL - KH));
                mma16816(S[2 * nt2],     qfh[dt], bh[0], bh[1]);
                mma16816(S[2 * nt2],     qfh[dt], bl[0], bl[1]);
                mma16816(S[2 * nt2],     qfl[dt], bh[0], bh[1]);
                mma16816(S[2 * nt2 + 1], qfh[dt], bh[2], bh[3]);
                mma16816(S[2 * nt2 + 1], qfh[dt], bl[2], bl[3]);
                mma16816(S[2 * nt2 + 1], qfl[dt], bh[2], bh[3]);
            }
        }

        // ---- online softmax (exp2 domain) ----
        float mx0 = -1e30f, mx1 = -1e30f;
#pragma unroll
        for (int t = 0; t < 16; t++) {
            S[t][0] *= SC; S[t][1] *= SC; S[t][2] *= SC; S[t][3] *= SC;
            mx0 = fmaxf(mx0, fmaxf(S[t][0], S[t][1]));
            mx1 = fmaxf(mx1, fmaxf(S[t][2], S[t][3]));
        }
        mx0 = fmaxf(mx0, __shfl_xor_sync(0xffffffffu, mx0, 1));
        mx0 = fmaxf(mx0, __shfl_xor_sync(0xffffffffu, mx0, 2));
        mx1 = fmaxf(mx1, __shfl_xor_sync(0xffffffffu, mx1, 1));
        mx1 = fmaxf(mx1, __shfl_xor_sync(0xffffffffu, mx1, 2));
        const float mn0 = fmaxf(mrow0, mx0), mn1 = fmaxf(mrow1, mx1);
        const float c0 = ex2(mrow0 - mn0), c1 = ex2(mrow1 - mn1);
        mrow0 = mn0; mrow1 = mn1;

        float sum0 = 0.f, sum1 = 0.f;
#pragma unroll
        for (int t = 0; t < 16; t++) {
            S[t][0] = ex2(S[t][0] - mn0); S[t][1] = ex2(S[t][1] - mn0);
            S[t][2] = ex2(S[t][2] - mn1); S[t][3] = ex2(S[t][3] - mn1);
            sum0 += S[t][0] + S[t][1];
            sum1 += S[t][2] + S[t][3];
        }
        sum0 += __shfl_xor_sync(0xffffffffu, sum0, 1);
        sum0 += __shfl_xor_sync(0xffffffffu, sum0, 2);
        sum1 += __shfl_xor_sync(0xffffffffu, sum1, 1);
        sum1 += __shfl_xor_sync(0xffffffffu, sum1, 2);
        lrow0 = lrow0 * c0 + sum0;
        lrow1 = lrow1 * c1 + sum1;
#pragma unroll
        for (int d = 0; d < 8; d++) {
            O[d][0] *= c0; O[d][1] *= c0; O[d][2] *= c1; O[d][3] *= c1;
        }

        // ---- P -> bf16 A-fragments (registers; acc layout == A-frag layout) ----
        uint32_t ph[8][4], pl[8][4];
#pragma unroll
        for (int kk = 0; kk < 8; kk++) {
            pack_hilo(S[2 * kk][0],     S[2 * kk][1],     ph[kk][0], pl[kk][0]);
            pack_hilo(S[2 * kk][2],     S[2 * kk][3],     ph[kk][1], pl[kk][1]);
            pack_hilo(S[2 * kk + 1][0], S[2 * kk + 1][1], ph[kk][2], pl[kk][2]);
            pack_hilo(S[2 * kk + 1][2], S[2 * kk + 1][3], ph[kk][3], pl[kk][3]);
        }

        // ---- O += P @ V (3-term) ----
#pragma unroll
        for (int kk = 0; kk < 8; kk++) {
#pragma unroll
            for (int dt2 = 0; dt2 < 4; dt2++) {
                const uint32_t rv = sb + VH + (kk * 16 + (lane & 15)) * ASTR +
                                    (dt2 * 16 + (lane >> 4) * 8) * 2;
                uint32_t vh[4], vl[4];
                ldsm4t(vh, rv);
                ldsm4t(vl, rv + (VL - VH));
                mma16816(O[2 * dt2],     ph[kk], vh[0], vh[1]);
                mma16816(O[2 * dt2],     pl[kk], vh[0], vh[1]);
                mma16816(O[2 * dt2],     ph[kk], vl[0], vl[1]);
                mma16816(O[2 * dt2 + 1], ph[kk], vh[2], vh[3]);
                mma16816(O[2 * dt2 + 1], pl[kk], vh[2], vh[3]);
                mma16816(O[2 * dt2 + 1], ph[kk], vl[2], vl[3]);
            }
        }
        __syncthreads();
    }

    // ---- epilogue: O /= l, hi/lo split, write ctx [t][b][H] ----
    const float i0 = 1.f / lrow0, i1 = 1.f / lrow1;
    const int g = lane >> 2, tq = (lane & 3) * 2;
    const int t0 = q0 + wid * 16 + g;
#pragma unroll
    for (int d = 0; d < 8; d++) {
        const int hcol = j * 64 + d * 8 + tq;
        const size_t idx0 = ((size_t)t0 * B + b) * H + hcol;
        const size_t idx1 = ((size_t)(t0 + 8) * B + b) * H + hcol;
        uint32_t h, l;
        pack_hilo(O[d][0] * i0, O[d][1] * i0, h, l);
        *(uint32_t*)(cxh + idx0) = h; *(uint32_t*)(cxl + idx0) = l;
        pack_hilo(O[d][2] * i1, O[d][3] * i1, h, l);
        *(uint32_t*)(cxh + idx1) = h; *(uint32_t*)(cxl + idx1) = l;
    }
}

// ---------------------------------------------------------------------------
extern "C" void kernel_launch(void* const* d_in, const int* in_sizes, int n_in,
                              void* d_out, int out_size)
{
    const float* inputs_q  = (const float*)d_in[0];
    const float* inputs_kv = (const float*)d_in[1];
    const float* w_q  = (const float*)d_in[2];
    const float* b_q  = (const float*)d_in[3];
    const float* w_kv = (const float*)d_in[4];
    const float* b_kv = (const float*)d_in[5];
    const float* w_o  = (const float*)d_in[6];
    const float* b_o  = (const float*)d_in[7];
    const float* r_q  = (const float*)d_in[8];
    const float* s_q  = (const float*)d_in[9];
    const float* r_kv = (const float*)d_in[10];
    const float* s_kv = (const float*)d_in[11];
    float* out = (float*)d_out;

    void* p;
    cudaGetSymbolAddress(&p, g_aq_h);  __nv_bfloat16* aqh = (__nv_bfloat16*)p;
    cudaGetSymbolAddress(&p, g_aq_l);  __nv_bfloat16* aql = (__nv_bfloat16*)p;
    cudaGetSymbolAddress(&p, g_akv_h); __nv_bfloat16* akh = (__nv_bfloat16*)p;
    cudaGetSymbolAddress(&p, g_akv_l); __nv_bfloat16* akl = (__nv_bfloat16*)p;
    cudaGetSymbolAddress(&p, g_wq_h);  __nv_bfloat16* wqh = (__nv_bfloat16*)p;
    cudaGetSymbolAddress(&p, g_wq_l);  __nv_bfloat16* wql = (__nv_bfloat16*)p;
    cudaGetSymbolAddress(&p, g_wkv_h); __nv_bfloat16* wkh = (__nv_bfloat16*)p;
    cudaGetSymbolAddress(&p, g_wkv_l); __nv_bfloat16* wkl = (__nv_bfloat16*)p;
    cudaGetSymbolAddress(&p, g_wo_h);  __nv_bfloat16* woh = (__nv_bfloat16*)p;
    cudaGetSymbolAddress(&p, g_wo_l);  __nv_bfloat16* wol = (__nv_bfloat16*)p;
    cudaGetSymbolAddress(&p, g_qh);    __nv_bfloat16* qh  = (__nv_bfloat16*)p;
    cudaGetSymbolAddress(&p, g_ql);    __nv_bfloat16* ql  = (__nv_bfloat16*)p;
    cudaGetSymbolAddress(&p, g_kvh);   __nv_bfloat16* kvh = (__nv_bfloat16*)p;
    cudaGetSymbolAddress(&p, g_kvl);   __nv_bfloat16* kvl = (__nv_bfloat16*)p;
    cudaGetSymbolAddress(&p, g_cxh);   __nv_bfloat16* cxh = (__nv_bfloat16*)p;
    cudaGetSymbolAddress(&p, g_cxl);   __nv_bfloat16* cxl = (__nv_bfloat16*)p;

    cudaFuncSetAttribute(gemm_mma_kernel, cudaFuncAttributeMaxDynamicSharedMemorySize, GEMM_SMEM);
    cudaFuncSetAttribute(attn_mma_kernel, cudaFuncAttributeMaxDynamicSharedMemorySize, ATTN_SMEM);

    const int act4 = TQ * B * H / 4;
    split_act_kernel<<<(act4 + 255) / 256, 256>>>(inputs_q,  r_q,  aqh, aql, TQ);
    split_act_kernel<<<(act4 + 255) / 256, 256>>>(inputs_kv, r_kv, akh, akl, TK);
    split_plain_kernel<<<(H * H / 4 + 255) / 256, 256>>>(w_q, wqh, wql, H * H / 4);
    split_plain_kernel<<<(2 * H * H / 4 + 255) / 256, 256>>>(w_kv, wkh, wkl, 2 * H * H / 4);
    split_plain_kernel<<<(H * H / 4 + 255) / 256, 256>>>(w_o, woh, wol, H * H / 4);

    // q projection -> bf16 hi/lo q [b][t][H]
    gemm_mma_kernel<<<dim3(8, 8, 8), 256, GEMM_SMEM>>>(
        aqh, aql, wqh, wql, TQ, nullptr, qh, ql,
        H, (long long)TQ * H, s_q, H, b_q);

    // kv projection -> bf16 hi/lo kv [b][t][2H]
    gemm_mma_kernel<<<dim3(16, 8, 8), 256, GEMM_SMEM>>>(
        akh, akl, wkh, wkl, TK, nullptr, kvh, kvl,
        2 * H, (long long)TK * 2 * H, s_kv, 2 * H, b_kv);

    // attention -> ctx bf16 hi/lo [t][b][H]
    attn_mma_kernel<<<dim3(8, 128), 256, ATTN_SMEM>>>(qh, ql, kvh, kvl, cxh, cxl);

    // output projection -> fp32 out [t*b][H]
    gemm_mma_kernel<<<dim3(8, 64, 1), 256, GEMM_SMEM>>>(
        cxh, cxl, woh, wol, TQ * B, out, nullptr, nullptr,
        H, 0LL, nullptr, 0, b_o);
}